// round 2
// baseline (speedup 1.0000x reference)
#include <cuda_runtime.h>

// ---------------- problem constants ----------------
#define BATCH 4
#define SEQ   2048
#define DMODEL 1024
#define NHEAD 16
#define DHEAD 64
#define FFDIM 4096
#define BS (BATCH*SEQ)          // 8192 rows
#define QKVN 3072               // 3 * NHEAD * DHEAD

// ---------------- device scratch (allocation-free rule: __device__ globals) ----------------
__device__ float g_wqkv[(size_t)DMODEL * QKVN];     // packed [D][3*H*DH]
__device__ float g_bqkv[QKVN];
__device__ float g_qkv [(size_t)BS * QKVN];         // [BS][3072]
__device__ float g_attn[(size_t)BS * DMODEL];       // concat-head attention out
__device__ float g_t1  [(size_t)BS * DMODEL];       // out-proj result
__device__ float g_y   [(size_t)BS * DMODEL];       // after LN1
__device__ float g_ff1 [(size_t)BS * FFDIM];
__device__ float g_ff2 [(size_t)BS * DMODEL];

// ---------------- pack wq/wk/wv -> [D][3*H*DH] ----------------
__global__ void pack_wqkv(const float* __restrict__ wq, const float* __restrict__ wk,
                          const float* __restrict__ wv, const float* __restrict__ bq,
                          const float* __restrict__ bk, const float* __restrict__ bv)
{
    int idx = blockIdx.x * blockDim.x + threadIdx.x;   // over H*D*DH = 1,048,576
    if (idx < NHEAD * DMODEL * DHEAD) {
        int e = idx & 63;
        int d = (idx >> 6) & 1023;
        int h = idx >> 16;
        int col = h * DHEAD + e;
        g_wqkv[(size_t)d * QKVN + col]            = wq[idx];
        g_wqkv[(size_t)d * QKVN + 1024 + col]     = wk[idx];
        g_wqkv[(size_t)d * QKVN + 2048 + col]     = wv[idx];
    }
    if (idx < NHEAD * DHEAD) {
        g_bqkv[idx]        = bq[idx];
        g_bqkv[1024 + idx] = bk[idx];
        g_bqkv[2048 + idx] = bv[idx];
    }
}

// ---------------- generic fp32 GEMM: C[M,N] = A[M,K] * B[K,N] + bias (opt relu) ----------------
// 128x128 block tile, BK=16, 256 threads, 8x8 per-thread micro-tile (split 4+4 halves
// so float4 smem reads are conflict-free).
__global__ __launch_bounds__(256) void gemm128(const float* __restrict__ A,
                                               const float* __restrict__ B,
                                               const float* __restrict__ bias,
                                               float* __restrict__ C,
                                               int M, int N, int K, int relu)
{
    __shared__ float As[16][128];   // As[k][m] (transposed on store)
    __shared__ float Bs[16][128];   // Bs[k][n]
    const int tid = threadIdx.x;
    const int m0 = blockIdx.y * 128, n0 = blockIdx.x * 128;
    const int tr = tid >> 4, tc = tid & 15;

    float acc[8][8];
#pragma unroll
    for (int i = 0; i < 8; i++)
#pragma unroll
        for (int j = 0; j < 8; j++) acc[i][j] = 0.f;

    for (int kk = 0; kk < K; kk += 16) {
#pragma unroll
        for (int it = 0; it < 2; it++) {
            int l  = tid + it * 256;
            int r  = l >> 2, c4 = (l & 3) * 4;          // A tile: 128 rows x 16 cols
            float4 av = *(const float4*)(A + (size_t)(m0 + r) * K + kk + c4);
            As[c4 + 0][r] = av.x; As[c4 + 1][r] = av.y;
            As[c4 + 2][r] = av.z; As[c4 + 3][r] = av.w;
            int rb = l >> 5, cb = (l & 31) * 4;         // B tile: 16 rows x 128 cols
            *(float4*)(&Bs[rb][cb]) = *(const float4*)(B + (size_t)(kk + rb) * N + n0 + cb);
        }
        __syncthreads();
#pragma unroll
        for (int k = 0; k < 16; k++) {
            float __align__(16) a[8], bf[8];
            *(float4*)&a[0]  = *(const float4*)&As[k][tr * 4];
            *(float4*)&a[4]  = *(const float4*)&As[k][64 + tr * 4];
            *(float4*)&bf[0] = *(const float4*)&Bs[k][tc * 4];
            *(float4*)&bf[4] = *(const float4*)&Bs[k][64 + tc * 4];
#pragma unroll
            for (int i = 0; i < 8; i++)
#pragma unroll
                for (int j = 0; j < 8; j++) acc[i][j] += a[i] * bf[j];
        }
        __syncthreads();
    }

    float bl[8];
#pragma unroll
    for (int j = 0; j < 4; j++) {
        bl[j]     = bias[n0 + tc * 4 + j];
        bl[4 + j] = bias[n0 + 64 + tc * 4 + j];
    }
#pragma unroll
    for (int i = 0; i < 8; i++) {
        int r = m0 + ((i & 4) << 4) + tr * 4 + (i & 3);
        float4 v0, v1;
        v0.x = acc[i][0] + bl[0]; v0.y = acc[i][1] + bl[1];
        v0.z = acc[i][2] + bl[2]; v0.w = acc[i][3] + bl[3];
        v1.x = acc[i][4] + bl[4]; v1.y = acc[i][5] + bl[5];
        v1.z = acc[i][6] + bl[6]; v1.w = acc[i][7] + bl[7];
        if (relu) {
            v0.x = fmaxf(v0.x, 0.f); v0.y = fmaxf(v0.y, 0.f);
            v0.z = fmaxf(v0.z, 0.f); v0.w = fmaxf(v0.w, 0.f);
            v1.x = fmaxf(v1.x, 0.f); v1.y = fmaxf(v1.y, 0.f);
            v1.z = fmaxf(v1.z, 0.f); v1.w = fmaxf(v1.w, 0.f);
        }
        *(float4*)(C + (size_t)r * N + n0 + tc * 4)      = v0;
        *(float4*)(C + (size_t)r * N + n0 + 64 + tc * 4) = v1;
    }
}

// ---------------- fused flash attention (fp32, 64q x 64k tiles, DH=64) ----------------
#define FP 68   // smem pitch (floats): 16B-aligned, conflict-free strided access
__global__ __launch_bounds__(256) void flash64(const float* __restrict__ qkv,
                                               float* __restrict__ out)
{
    extern __shared__ float sm[];
    float* Qs = sm;                 // [64][FP] rows = query, cols = dh (pre-scaled)
    float* Ks = sm + 64 * FP;       // [64][FP] rows = dh, cols = key (transposed)
    float* Vs = sm + 2 * 64 * FP;   // [64][FP] rows = key, cols = dh
    float* Ps = sm + 3 * 64 * FP;   // [64][FP] probs

    const int qt = blockIdx.x, bh = blockIdx.y;
    const int b = bh >> 4, h = bh & 15;
    const int q0 = qt * 64;
    const int tid = threadIdx.x;
    const int tr = tid >> 4, tc = tid & 15;

    const size_t base = (size_t)b * SEQ * QKVN + (size_t)h * DHEAD;
    const float* Qg = qkv + base;
    const float* Kg = qkv + base + 1024;
    const float* Vg = qkv + base + 2048;

    // load Q tile, pre-scaled by 1/sqrt(64)
    for (int i = tid; i < 64 * 16; i += 256) {
        int r = i >> 4, c4 = (i & 15) * 4;
        float4 v = *(const float4*)(Qg + (size_t)(q0 + r) * QKVN + c4);
        v.x *= 0.125f; v.y *= 0.125f; v.z *= 0.125f; v.w *= 0.125f;
        *(float4*)&Qs[r * FP + c4] = v;
    }

    float m_run[4], l_run[4], o[4][4];
#pragma unroll
    for (int i = 0; i < 4; i++) {
        m_run[i] = -1e30f; l_run[i] = 0.f;
#pragma unroll
        for (int j = 0; j < 4; j++) o[i][j] = 0.f;
    }

    for (int kt = 0; kt < SEQ; kt += 64) {
        __syncthreads();   // prior iteration consumers done (also covers Q load, 1st iter)
        for (int i = tid; i < 64 * 16; i += 256) {
            int r = i >> 4, c4 = (i & 15) * 4;
            float4 kv = *(const float4*)(Kg + (size_t)(kt + r) * QKVN + c4);
            Ks[(c4 + 0) * FP + r] = kv.x;
            Ks[(c4 + 1) * FP + r] = kv.y;
            Ks[(c4 + 2) * FP + r] = kv.z;
            Ks[(c4 + 3) * FP + r] = kv.w;
            *(float4*)&Vs[r * FP + c4] = *(const float4*)(Vg + (size_t)(kt + r) * QKVN + c4);
        }
        __syncthreads();

        // S = Q * K^T  (each thread: rows tr*4.., key-cols tc*4..)
        float s[4][4];
#pragma unroll
        for (int i = 0; i < 4; i++)
#pragma unroll
            for (int j = 0; j < 4; j++) s[i][j] = 0.f;

        for (int k = 0; k < 64; k += 4) {
            float __align__(16) qv[4][4], kf[4][4];
#pragma unroll
            for (int i = 0; i < 4; i++)
                *(float4*)qv[i] = *(const float4*)&Qs[(tr * 4 + i) * FP + k];
#pragma unroll
            for (int t = 0; t < 4; t++)
                *(float4*)kf[t] = *(const float4*)&Ks[(k + t) * FP + tc * 4];
#pragma unroll
            for (int i = 0; i < 4; i++)
#pragma unroll
                for (int t = 0; t < 4; t++)
#pragma unroll
                    for (int j = 0; j < 4; j++) s[i][j] += qv[i][t] * kf[t][j];
        }

        // online softmax (row groups of 16 threads; xor<16 stays in-group)
#pragma unroll
        for (int i = 0; i < 4; i++) {
            float mx = fmaxf(fmaxf(s[i][0], s[i][1]), fmaxf(s[i][2], s[i][3]));
#pragma unroll
            for (int mm = 1; mm < 16; mm <<= 1)
                mx = fmaxf(mx, __shfl_xor_sync(0xffffffffu, mx, mm));
            float mnew = fmaxf(m_run[i], mx);
            float corr = __expf(m_run[i] - mnew);
            float ls = 0.f;
#pragma unroll
            for (int j = 0; j < 4; j++) {
                float p = __expf(s[i][j] - mnew);
                s[i][j] = p; ls += p;
            }
#pragma unroll
            for (int mm = 1; mm < 16; mm <<= 1)
                ls += __shfl_xor_sync(0xffffffffu, ls, mm);
            m_run[i] = mnew;
            l_run[i] = l_run[i] * corr + ls;
#pragma unroll
            for (int j = 0; j < 4; j++) o[i][j] *= corr;
            *(float4*)&Ps[(tr * 4 + i) * FP + tc * 4] =
                make_float4(s[i][0], s[i][1], s[i][2], s[i][3]);
        }
        __syncthreads();

        // O += P * V  (each thread: rows tr*4.., dh-cols tc*4..)
        for (int k = 0; k < 64; k += 4) {
            float __align__(16) pf[4][4], vf[4][4];
#pragma unroll
            for (int i = 0; i < 4; i++)
                *(float4*)pf[i] = *(const float4*)&Ps[(tr * 4 + i) * FP + k];
#pragma unroll
            for (int t = 0; t < 4; t++)
                *(float4*)vf[t] = *(const float4*)&Vs[(k + t) * FP + tc * 4];
#pragma unroll
            for (int i = 0; i < 4; i++)
#pragma unroll
                for (int t = 0; t < 4; t++)
#pragma unroll
                    for (int j = 0; j < 4; j++) o[i][j] += pf[i][t] * vf[t][j];
        }
    }

#pragma unroll
    for (int i = 0; i < 4; i++) {
        float inv = 1.0f / l_run[i];
        size_t off = ((size_t)(b * SEQ + q0 + tr * 4 + i)) * DMODEL + h * DHEAD + tc * 4;
        *(float4*)(out + off) =
            make_float4(o[i][0] * inv, o[i][1] * inv, o[i][2] * inv, o[i][3] * inv);
    }
}

// ---------------- residual add + LayerNorm ----------------
__global__ __launch_bounds__(256) void add_ln(const float* __restrict__ a,
                                              const float* __restrict__ resid,
                                              const float* __restrict__ g,
                                              const float* __restrict__ bb,
                                              float* __restrict__ out)
{
    const int row = blockIdx.x;
    const int tid = threadIdx.x;
    const float* ar = a     + (size_t)row * DMODEL;
    const float* rr = resid + (size_t)row * DMODEL;

    float v[4], s = 0.f, sq = 0.f;
#pragma unroll
    for (int u = 0; u < 4; u++) {
        int c = u * 256 + tid;
        float t = ar[c] + rr[c];
        v[u] = t; s += t; sq += t * t;
    }
#pragma unroll
    for (int mm = 16; mm; mm >>= 1) {
        s  += __shfl_xor_sync(0xffffffffu, s, mm);
        sq += __shfl_xor_sync(0xffffffffu, sq, mm);
    }
    __shared__ float rs[8], rq[8];
    int w = tid >> 5, l = tid & 31;
    if (l == 0) { rs[w] = s; rq[w] = sq; }
    __syncthreads();
    s = 0.f; sq = 0.f;
#pragma unroll
    for (int i = 0; i < 8; i++) { s += rs[i]; sq += rq[i]; }

    float mean = s * (1.f / DMODEL);
    float var  = sq * (1.f / DMODEL) - mean * mean;
    float rstd = rsqrtf(var + 1e-5f);
    float* orow = out + (size_t)row * DMODEL;
#pragma unroll
    for (int u = 0; u < 4; u++) {
        int c = u * 256 + tid;
        orow[c] = (v[u] - mean) * rstd * g[c] + bb[c];
    }
}

// ---------------- launch ----------------
extern "C" void kernel_launch(void* const* d_in, const int* in_sizes, int n_in,
                              void* d_out, int out_size)
{
    const float* x    = (const float*)d_in[0];
    const float* wq   = (const float*)d_in[1];
    const float* bq   = (const float*)d_in[2];
    const float* wk   = (const float*)d_in[3];
    const float* bk   = (const float*)d_in[4];
    const float* wv   = (const float*)d_in[5];
    const float* bv   = (const float*)d_in[6];
    const float* wo   = (const float*)d_in[7];
    const float* bo   = (const float*)d_in[8];
    const float* ln1g = (const float*)d_in[9];
    const float* ln1b = (const float*)d_in[10];
    const float* w1   = (const float*)d_in[11];
    const float* b1   = (const float*)d_in[12];
    const float* w2   = (const float*)d_in[13];
    const float* b2   = (const float*)d_in[14];
    const float* ln2g = (const float*)d_in[15];
    const float* ln2b = (const float*)d_in[16];
    float* out = (float*)d_out;

    float *wqkv, *bqkv, *qkv, *attn, *t1, *y, *ff1, *ff2;
    cudaGetSymbolAddress((void**)&wqkv, g_wqkv);
    cudaGetSymbolAddress((void**)&bqkv, g_bqkv);
    cudaGetSymbolAddress((void**)&qkv,  g_qkv);
    cudaGetSymbolAddress((void**)&attn, g_attn);
    cudaGetSymbolAddress((void**)&t1,   g_t1);
    cudaGetSymbolAddress((void**)&y,    g_y);
    cudaGetSymbolAddress((void**)&ff1,  g_ff1);
    cudaGetSymbolAddress((void**)&ff2,  g_ff2);

    const int smem_flash = 4 * 64 * FP * 4;   // 69632 B
    cudaFuncSetAttribute(flash64, cudaFuncAttributeMaxDynamicSharedMemorySize, smem_flash);

    // 1) pack QKV weights/biases
    pack_wqkv<<<(NHEAD * DMODEL * DHEAD + 255) / 256, 256>>>(wq, wk, wv, bq, bk, bv);
    // 2) QKV projection: [8192,1024] x [1024,3072]
    gemm128<<<dim3(QKVN / 128, BS / 128), 256>>>(x, wqkv, bqkv, qkv, BS, QKVN, DMODEL, 0);
    // 3) fused flash attention -> concat-head output [8192,1024]
    flash64<<<dim3(SEQ / 64, BATCH * NHEAD), 256, smem_flash>>>(qkv, attn);
    // 4) output projection
    gemm128<<<dim3(DMODEL / 128, BS / 128), 256>>>(attn, wo, bo, t1, BS, DMODEL, DMODEL, 0);
    // 5) residual + LN1
    add_ln<<<BS, 256>>>(t1, x, ln1g, ln1b, y);
    // 6) FFN up (bias + relu fused)
    gemm128<<<dim3(FFDIM / 128, BS / 128), 256>>>(y, w1, b1, ff1, BS, FFDIM, DMODEL, 1);
    // 7) FFN down
    gemm128<<<dim3(DMODEL / 128, BS / 128), 256>>>(ff1, w2, b2, ff2, BS, DMODEL, FFDIM, 0);
    // 8) residual + LN2 -> final output
    add_ln<<<BS, 256>>>(ff2, y, ln2g, ln2b, out);
}

// round 4
// speedup vs baseline: 1.6720x; 1.6720x over previous
#include <cuda_runtime.h>
#include <cstdint>

// ---------------- problem constants ----------------
#define BATCH 4
#define SEQ   2048
#define DMODEL 1024
#define NHEAD 16
#define DHEAD 64
#define FFDIM 4096
#define BS (BATCH*SEQ)          // 8192 rows
#define QKVN 3072               // 3 * NHEAD * DHEAD

// ---------------- device scratch ----------------
__device__ float g_wqkvT[(size_t)QKVN * DMODEL];   // [N=3072][K=1024], tf32-rounded
__device__ float g_bqkv [QKVN];
__device__ float g_woT  [(size_t)DMODEL * DMODEL];
__device__ float g_w1T  [(size_t)FFDIM * DMODEL];
__device__ float g_w2T  [(size_t)DMODEL * FFDIM];
__device__ float g_xr   [(size_t)BS * DMODEL];     // x rounded to tf32
__device__ float g_qkv  [(size_t)BS * QKVN];
__device__ float g_attn [(size_t)BS * DMODEL];     // rounded in flash epilogue
__device__ float g_t1   [(size_t)BS * DMODEL];
__device__ float g_y    [(size_t)BS * DMODEL];
__device__ float g_yr   [(size_t)BS * DMODEL];     // rounded for FFN1
__device__ float g_ff1  [(size_t)BS * FFDIM];      // rounded in GEMM epilogue
__device__ float g_ff2  [(size_t)BS * DMODEL];

// ---------------- helpers ----------------
__device__ __forceinline__ uint32_t smem_u32(const void* p) {
    uint32_t a;
    asm("{ .reg .u64 t; cvta.to.shared.u64 t, %1; cvt.u32.u64 %0, t; }" : "=r"(a) : "l"(p));
    return a;
}
__device__ __forceinline__ float rtf32(float x) {   // round-to-nearest tf32
    uint32_t r;
    asm("cvt.rna.tf32.f32 %0, %1;" : "=r"(r) : "f"(x));
    return __uint_as_float(r);
}
__device__ __forceinline__ void cp16(uint32_t sdst, const void* gsrc) {
    asm volatile("cp.async.cg.shared.global [%0], [%1], 16;" :: "r"(sdst), "l"(gsrc) : "memory");
}
__device__ __forceinline__ void mma_tf32(float* c, const float* a, const float* b) {
    asm volatile(
        "mma.sync.aligned.m16n8k8.row.col.f32.tf32.tf32.f32 "
        "{%0,%1,%2,%3}, {%4,%5,%6,%7}, {%8,%9}, {%0,%1,%2,%3};"
        : "+f"(c[0]), "+f"(c[1]), "+f"(c[2]), "+f"(c[3])
        : "r"(__float_as_uint(a[0])), "r"(__float_as_uint(a[1])),
          "r"(__float_as_uint(a[2])), "r"(__float_as_uint(a[3])),
          "r"(__float_as_uint(b[0])), "r"(__float_as_uint(b[1])));
}

// ---------------- weight prep ----------------
__global__ void pack_wqkvT(const float* __restrict__ wq, const float* __restrict__ wk,
                           const float* __restrict__ wv, const float* __restrict__ bq,
                           const float* __restrict__ bk, const float* __restrict__ bv)
{
    int idx = blockIdx.x * blockDim.x + threadIdx.x;   // H*D*DH = 1,048,576
    if (idx < NHEAD * DMODEL * DHEAD) {
        int e = idx & 63;
        int d = (idx >> 6) & 1023;
        int h = idx >> 16;
        int row = h * DHEAD + e;
        g_wqkvT[(size_t)row * DMODEL + d]          = rtf32(wq[idx]);
        g_wqkvT[(size_t)(1024 + row) * DMODEL + d] = rtf32(wk[idx]);
        g_wqkvT[(size_t)(2048 + row) * DMODEL + d] = rtf32(wv[idx]);
    }
    if (idx < NHEAD * DHEAD) {
        g_bqkv[idx]        = bq[idx];
        g_bqkv[1024 + idx] = bk[idx];
        g_bqkv[2048 + idx] = bv[idx];
    }
}

// transpose [R][C] -> [C][R] with tf32 rounding
__global__ void transpose_round(const float* __restrict__ in, float* __restrict__ out,
                                int R, int C)
{
    __shared__ float t[32][33];
    int c0 = blockIdx.x * 32, r0 = blockIdx.y * 32;
    int x = threadIdx.x, y = threadIdx.y;   // 32 x 8
#pragma unroll
    for (int i = 0; i < 32; i += 8)
        t[y + i][x] = in[(size_t)(r0 + y + i) * C + c0 + x];
    __syncthreads();
#pragma unroll
    for (int i = 0; i < 32; i += 8)
        out[(size_t)(c0 + y + i) * R + r0 + x] = rtf32(t[x][y + i]);
}

__global__ void round_copy(const float* __restrict__ in, float* __restrict__ out, int n4)
{
    int i = blockIdx.x * blockDim.x + threadIdx.x;
    if (i < n4) {
        float4 v = ((const float4*)in)[i];
        v.x = rtf32(v.x); v.y = rtf32(v.y); v.z = rtf32(v.z); v.w = rtf32(v.w);
        ((float4*)out)[i] = v;
    }
}

// ---------------- mma.sync tf32 GEMM: C[M,N] = A[M,K] * Bt[N,K]^T + bias ----------------
// BM=128, BN=128, BK=16 (two k8 sub-steps). 256 threads = 8 warps in 2(m) x 4(n),
// each warp 64x32 via 4x4 m16n8k8 tiles. Double-buffered cp.async.
// flags: bit0 = relu, bit1 = round output to tf32
#define PADK 20                       // floats per smem row: conflict-free + 16B aligned
#define TILEF (128 * PADK)            // floats per tile buffer

__device__ __forceinline__ void ld_tile(const float* g, int ldK, uint32_t sdst, int tid)
{
    // 128 rows x 16 floats; 512 16B-chunks over 256 threads
#pragma unroll
    for (int it = 0; it < 2; it++) {
        int c   = tid + it * 256;
        int row = c >> 2, q = c & 3;
        cp16(sdst + (uint32_t)(row * PADK + q * 4) * 4, g + (size_t)row * ldK + q * 4);
    }
}

__global__ __launch_bounds__(256)
void gemm_mma(const float* __restrict__ A, const float* __restrict__ B,
              const float* __restrict__ bias, float* __restrict__ C,
              int M, int N, int K, int flags)
{
    __shared__ float As[2][TILEF];
    __shared__ float Bs[2][TILEF];

    const int tid  = threadIdx.x;
    const int lane = tid & 31, wid = tid >> 5;
    const int grp  = lane >> 2, tg = lane & 3;
    const int wm   = wid & 1,  wn = wid >> 1;     // warp tile origin (wm*64, wn*32)
    const int m0   = blockIdx.y * 128, n0 = blockIdx.x * 128;

    const float* Abase = A + (size_t)m0 * K;
    const float* Bbase = B + (size_t)n0 * K;
    const uint32_t sA = smem_u32(As), sB = smem_u32(Bs);

    float acc[4][4][4];
#pragma unroll
    for (int i = 0; i < 4; i++)
#pragma unroll
        for (int j = 0; j < 4; j++)
#pragma unroll
            for (int r = 0; r < 4; r++) acc[i][j][r] = 0.f;

    const int nk = K >> 4;
    ld_tile(Abase, K, sA, tid);
    ld_tile(Bbase, K, sB, tid);
    asm volatile("cp.async.commit_group;" ::: "memory");

    for (int kk = 0; kk < nk; kk++) {
        const int buf = kk & 1;
        if (kk + 1 < nk) {
            ld_tile(Abase + (kk + 1) * 16, K, sA + (1 - buf) * TILEF * 4, tid);
            ld_tile(Bbase + (kk + 1) * 16, K, sB + (1 - buf) * TILEF * 4, tid);
            asm volatile("cp.async.commit_group;" ::: "memory");
            asm volatile("cp.async.wait_group 1;" ::: "memory");
        } else {
            asm volatile("cp.async.wait_group 0;" ::: "memory");
        }
        __syncthreads();

        const float* as = As[buf];
        const float* bs = Bs[buf];
#pragma unroll
        for (int s = 0; s < 2; s++) {
            float a[4][4], b[4][2];
#pragma unroll
            for (int mt = 0; mt < 4; mt++) {
                int base = (wm * 64 + mt * 16 + grp) * PADK + s * 8 + tg;
                a[mt][0] = as[base];
                a[mt][1] = as[base + 8 * PADK];
                a[mt][2] = as[base + 4];
                a[mt][3] = as[base + 8 * PADK + 4];
            }
#pragma unroll
            for (int nt = 0; nt < 4; nt++) {
                int base = (wn * 32 + nt * 8 + grp) * PADK + s * 8 + tg;
                b[nt][0] = bs[base];
                b[nt][1] = bs[base + 4];
            }
#pragma unroll
            for (int mt = 0; mt < 4; mt++)
#pragma unroll
                for (int nt = 0; nt < 4; nt++)
                    mma_tf32(acc[mt][nt], a[mt], b[nt]);
        }
        __syncthreads();
    }

    // epilogue
    const int relu = flags & 1, rnd = flags & 2;
#pragma unroll
    for (int mt = 0; mt < 4; mt++) {
#pragma unroll
        for (int nt = 0; nt < 4; nt++) {
            int row = m0 + wm * 64 + mt * 16 + grp;
            int col = n0 + wn * 32 + nt * 8 + tg * 2;
            float b0 = bias[col], b1 = bias[col + 1];
#pragma unroll
            for (int half = 0; half < 2; half++) {
                float v0 = acc[mt][nt][half * 2 + 0] + b0;
                float v1 = acc[mt][nt][half * 2 + 1] + b1;
                if (relu) { v0 = fmaxf(v0, 0.f); v1 = fmaxf(v1, 0.f); }
                if (rnd)  { v0 = rtf32(v0); v1 = rtf32(v1); }
                *(float2*)(C + (size_t)(row + half * 8) * N + col) = make_float2(v0, v1);
            }
        }
    }
}

// ---------------- fused flash attention (fp32, 64q x 64k tiles, DH=64) ----------------
#define FP 68
__global__ __launch_bounds__(256) void flash64(const float* __restrict__ qkv,
                                               float* __restrict__ out)
{
    extern __shared__ float sm[];
    float* Qs = sm;
    float* Ks = sm + 64 * FP;
    float* Vs = sm + 2 * 64 * FP;
    float* Ps = sm + 3 * 64 * FP;

    const int qt = blockIdx.x, bh = blockIdx.y;
    const int b = bh >> 4, h = bh & 15;
    const int q0 = qt * 64;
    const int tid = threadIdx.x;
    const int tr = tid >> 4, tc = tid & 15;

    const size_t base = (size_t)b * SEQ * QKVN + (size_t)h * DHEAD;
    const float* Qg = qkv + base;
    const float* Kg = qkv + base + 1024;
    const float* Vg = qkv + base + 2048;

    for (int i = tid; i < 64 * 16; i += 256) {
        int r = i >> 4, c4 = (i & 15) * 4;
        float4 v = *(const float4*)(Qg + (size_t)(q0 + r) * QKVN + c4);
        v.x *= 0.125f; v.y *= 0.125f; v.z *= 0.125f; v.w *= 0.125f;
        *(float4*)&Qs[r * FP + c4] = v;
    }

    float m_run[4], l_run[4], o[4][4];
#pragma unroll
    for (int i = 0; i < 4; i++) {
        m_run[i] = -1e30f; l_run[i] = 0.f;
#pragma unroll
        for (int j = 0; j < 4; j++) o[i][j] = 0.f;
    }

    for (int kt = 0; kt < SEQ; kt += 64) {
        __syncthreads();
        for (int i = tid; i < 64 * 16; i += 256) {
            int r = i >> 4, c4 = (i & 15) * 4;
            float4 kv = *(const float4*)(Kg + (size_t)(kt + r) * QKVN + c4);
            Ks[(c4 + 0) * FP + r] = kv.x;
            Ks[(c4 + 1) * FP + r] = kv.y;
            Ks[(c4 + 2) * FP + r] = kv.z;
            Ks[(c4 + 3) * FP + r] = kv.w;
            *(float4*)&Vs[r * FP + c4] = *(const float4*)(Vg + (size_t)(kt + r) * QKVN + c4);
        }
        __syncthreads();

        float s[4][4];
#pragma unroll
        for (int i = 0; i < 4; i++)
#pragma unroll
            for (int j = 0; j < 4; j++) s[i][j] = 0.f;

        for (int k = 0; k < 64; k += 4) {
            float __align__(16) qv[4][4], kf[4][4];
#pragma unroll
            for (int i = 0; i < 4; i++)
                *(float4*)qv[i] = *(const float4*)&Qs[(tr * 4 + i) * FP + k];
#pragma unroll
            for (int t = 0; t < 4; t++)
                *(float4*)kf[t] = *(const float4*)&Ks[(k + t) * FP + tc * 4];
#pragma unroll
            for (int i = 0; i < 4; i++)
#pragma unroll
                for (int t = 0; t < 4; t++)
#pragma unroll
                    for (int j = 0; j < 4; j++) s[i][j] += qv[i][t] * kf[t][j];
        }

#pragma unroll
        for (int i = 0; i < 4; i++) {
            float mx = fmaxf(fmaxf(s[i][0], s[i][1]), fmaxf(s[i][2], s[i][3]));
#pragma unroll
            for (int mm = 1; mm < 16; mm <<= 1)
                mx = fmaxf(mx, __shfl_xor_sync(0xffffffffu, mx, mm));
            float mnew = fmaxf(m_run[i], mx);
            float corr = __expf(m_run[i] - mnew);
            float ls = 0.f;
#pragma unroll
            for (int j = 0; j < 4; j++) {
                float p = __expf(s[i][j] - mnew);
                s[i][j] = p; ls += p;
            }
#pragma unroll
            for (int mm = 1; mm < 16; mm <<= 1)
                ls += __shfl_xor_sync(0xffffffffu, ls, mm);
            m_run[i] = mnew;
            l_run[i] = l_run[i] * corr + ls;
#pragma unroll
            for (int j = 0; j < 4; j++) o[i][j] *= corr;
            *(float4*)&Ps[(tr * 4 + i) * FP + tc * 4] =
                make_float4(s[i][0], s[i][1], s[i][2], s[i][3]);
        }
        __syncthreads();

        for (int k = 0; k < 64; k += 4) {
            float __align__(16) pf[4][4], vf[4][4];
#pragma unroll
            for (int i = 0; i < 4; i++)
                *(float4*)pf[i] = *(const float4*)&Ps[(tr * 4 + i) * FP + k];
#pragma unroll
            for (int t = 0; t < 4; t++)
                *(float4*)vf[t] = *(const float4*)&Vs[(k + t) * FP + tc * 4];
#pragma unroll
            for (int i = 0; i < 4; i++)
#pragma unroll
                for (int t = 0; t < 4; t++)
#pragma unroll
                    for (int j = 0; j < 4; j++) o[i][j] += pf[i][t] * vf[t][j];
        }
    }

#pragma unroll
    for (int i = 0; i < 4; i++) {
        float inv = 1.0f / l_run[i];
        size_t off = ((size_t)(b * SEQ + q0 + tr * 4 + i)) * DMODEL + h * DHEAD + tc * 4;
        *(float4*)(out + off) = make_float4(rtf32(o[i][0] * inv), rtf32(o[i][1] * inv),
                                            rtf32(o[i][2] * inv), rtf32(o[i][3] * inv));
    }
}

// ---------------- residual add + LayerNorm (+ optional tf32-rounded copy) ----------------
__global__ __launch_bounds__(256) void add_ln(const float* __restrict__ a,
                                              const float* __restrict__ resid,
                                              const float* __restrict__ g,
                                              const float* __restrict__ bb,
                                              float* __restrict__ out,
                                              float* __restrict__ out_r)
{
    const int row = blockIdx.x;
    const int tid = threadIdx.x;
    const float* ar = a     + (size_t)row * DMODEL;
    const float* rr = resid + (size_t)row * DMODEL;

    float v[4], s = 0.f, sq = 0.f;
#pragma unroll
    for (int u = 0; u < 4; u++) {
        int c = u * 256 + tid;
        float t = ar[c] + rr[c];
        v[u] = t; s += t; sq += t * t;
    }
#pragma unroll
    for (int mm = 16; mm; mm >>= 1) {
        s  += __shfl_xor_sync(0xffffffffu, s, mm);
        sq += __shfl_xor_sync(0xffffffffu, sq, mm);
    }
    __shared__ float rs[8], rq[8];
    int w = tid >> 5, l = tid & 31;
    if (l == 0) { rs[w] = s; rq[w] = sq; }
    __syncthreads();
    s = 0.f; sq = 0.f;
#pragma unroll
    for (int i = 0; i < 8; i++) { s += rs[i]; sq += rq[i]; }

    float mean = s * (1.f / DMODEL);
    float var  = sq * (1.f / DMODEL) - mean * mean;
    float rstd = rsqrtf(var + 1e-5f);
    float* orow = out + (size_t)row * DMODEL;
#pragma unroll
    for (int u = 0; u < 4; u++) {
        int c = u * 256 + tid;
        float ov = (v[u] - mean) * rstd * g[c] + bb[c];
        orow[c] = ov;
        if (out_r) out_r[(size_t)row * DMODEL + c] = rtf32(ov);
    }
}

// ---------------- launch ----------------
extern "C" void kernel_launch(void* const* d_in, const int* in_sizes, int n_in,
                              void* d_out, int out_size)
{
    const float* x    = (const float*)d_in[0];
    const float* wq   = (const float*)d_in[1];
    const float* bq   = (const float*)d_in[2];
    const float* wk   = (const float*)d_in[3];
    const float* bk   = (const float*)d_in[4];
    const float* wv   = (const float*)d_in[5];
    const float* bv   = (const float*)d_in[6];
    const float* wo   = (const float*)d_in[7];
    const float* bo   = (const float*)d_in[8];
    const float* ln1g = (const float*)d_in[9];
    const float* ln1b = (const float*)d_in[10];
    const float* w1   = (const float*)d_in[11];
    const float* b1   = (const float*)d_in[12];
    const float* w2   = (const float*)d_in[13];
    const float* b2   = (const float*)d_in[14];
    const float* ln2g = (const float*)d_in[15];
    const float* ln2b = (const float*)d_in[16];
    float* out = (float*)d_out;

    float *wqkvT, *bqkv, *woT, *w1T, *w2T, *xr, *qkv, *attn, *t1, *y, *yr, *ff1, *ff2;
    cudaGetSymbolAddress((void**)&wqkvT, g_wqkvT);
    cudaGetSymbolAddress((void**)&bqkv,  g_bqkv);
    cudaGetSymbolAddress((void**)&woT,   g_woT);
    cudaGetSymbolAddress((void**)&w1T,   g_w1T);
    cudaGetSymbolAddress((void**)&w2T,   g_w2T);
    cudaGetSymbolAddress((void**)&xr,    g_xr);
    cudaGetSymbolAddress((void**)&qkv,   g_qkv);
    cudaGetSymbolAddress((void**)&attn,  g_attn);
    cudaGetSymbolAddress((void**)&t1,    g_t1);
    cudaGetSymbolAddress((void**)&y,     g_y);
    cudaGetSymbolAddress((void**)&yr,    g_yr);
    cudaGetSymbolAddress((void**)&ff1,   g_ff1);
    cudaGetSymbolAddress((void**)&ff2,   g_ff2);

    const int smem_flash = 4 * 64 * FP * 4;
    cudaFuncSetAttribute(flash64, cudaFuncAttributeMaxDynamicSharedMemorySize, smem_flash);

    // weight prep + activation rounding (all tf32-rounded at rest)
    pack_wqkvT<<<(NHEAD * DMODEL * DHEAD + 255) / 256, 256>>>(wq, wk, wv, bq, bk, bv);
    transpose_round<<<dim3(DMODEL / 32, DMODEL / 32), dim3(32, 8)>>>(wo, woT, DMODEL, DMODEL);
    transpose_round<<<dim3(FFDIM / 32, DMODEL / 32), dim3(32, 8)>>>(w1, w1T, DMODEL, FFDIM);
    transpose_round<<<dim3(DMODEL / 32, FFDIM / 32), dim3(32, 8)>>>(w2, w2T, FFDIM, DMODEL);
    round_copy<<<(BS * DMODEL / 4 + 255) / 256, 256>>>(x, xr, BS * DMODEL / 4);

    // 1) QKV projection
    gemm_mma<<<dim3(QKVN / 128, BS / 128), 256>>>(xr, wqkvT, bqkv, qkv, BS, QKVN, DMODEL, 0);
    // 2) flash attention (tf32-rounded output)
    flash64<<<dim3(SEQ / 64, BATCH * NHEAD), 256, smem_flash>>>(qkv, attn);
    // 3) output projection
    gemm_mma<<<dim3(DMODEL / 128, BS / 128), 256>>>(attn, woT, bo, t1, BS, DMODEL, DMODEL, 0);
    // 4) residual + LN1 (fp32 y + rounded yr)
    add_ln<<<BS, 256>>>(t1, x, ln1g, ln1b, y, yr);
    // 5) FFN up: bias+relu fused, output rounded for FFN2
    gemm_mma<<<dim3(FFDIM / 128, BS / 128), 256>>>(yr, w1T, b1, ff1, BS, FFDIM, DMODEL, 3);
    // 6) FFN down
    gemm_mma<<<dim3(DMODEL / 128, BS / 128), 256>>>(ff1, w2T, b2, ff2, BS, DMODEL, FFDIM, 0);
    // 7) residual + LN2 -> final output
    add_ln<<<BS, 256>>>(ff2, y, ln2g, ln2b, out, nullptr);
}

// round 6
// speedup vs baseline: 5.4006x; 3.2301x over previous
#include <cuda_runtime.h>
#include <cuda_fp16.h>
#include <cstdint>

// ---------------- problem constants ----------------
#define BATCH 4
#define SEQ   2048
#define DMODEL 1024
#define NHEAD 16
#define DHEAD 64
#define FFDIM 4096
#define BS (BATCH*SEQ)
#define QKVN 3072
#define QSCALE 0.1803368801111204f   // log2(e) / sqrt(64)

// ---------------- device scratch ----------------
__device__ __half g_wqkvT[(size_t)QKVN * DMODEL];   // [N=3072][K=1024] (q part pre-scaled)
__device__ float  g_bqkv [QKVN];                    // q part pre-scaled
__device__ __half g_woT  [(size_t)DMODEL * DMODEL];
__device__ __half g_w1T  [(size_t)FFDIM * DMODEL];
__device__ __half g_w2T  [(size_t)DMODEL * FFDIM];
__device__ __half g_xh   [(size_t)BS * DMODEL];
__device__ __half g_qkvh [(size_t)BS * QKVN];
__device__ __half g_attnh[(size_t)BS * DMODEL];
__device__ float  g_t1   [(size_t)BS * DMODEL];
__device__ float  g_y    [(size_t)BS * DMODEL];
__device__ __half g_yh   [(size_t)BS * DMODEL];
__device__ __half g_ff1h [(size_t)BS * FFDIM];
__device__ float  g_ff2  [(size_t)BS * DMODEL];

// ---------------- helpers ----------------
__device__ __forceinline__ uint32_t smem_u32(const void* p) {
    uint32_t a;
    asm("{ .reg .u64 t; cvta.to.shared.u64 t, %1; cvt.u32.u64 %0, t; }" : "=r"(a) : "l"(p));
    return a;
}
__device__ __forceinline__ void cp16(uint32_t sdst, const void* gsrc) {
    asm volatile("cp.async.cg.shared.global [%0], [%1], 16;" :: "r"(sdst), "l"(gsrc) : "memory");
}
__device__ __forceinline__ void mma_f16(float* c, const uint32_t* a, const uint32_t* b) {
    asm volatile(
        "mma.sync.aligned.m16n8k16.row.col.f32.f16.f16.f32 "
        "{%0,%1,%2,%3}, {%4,%5,%6,%7}, {%8,%9}, {%0,%1,%2,%3};"
        : "+f"(c[0]), "+f"(c[1]), "+f"(c[2]), "+f"(c[3])
        : "r"(a[0]), "r"(a[1]), "r"(a[2]), "r"(a[3]), "r"(b[0]), "r"(b[1]));
}
#define LDSM4(r0, r1, r2, r3, addr) \
    asm volatile("ldmatrix.sync.aligned.m8n8.x4.shared.b16 {%0,%1,%2,%3}, [%4];" \
                 : "=r"(r0), "=r"(r1), "=r"(r2), "=r"(r3) : "r"(addr))
#define LDSM4T(r0, r1, r2, r3, addr) \
    asm volatile("ldmatrix.sync.aligned.m8n8.x4.trans.shared.b16 {%0,%1,%2,%3}, [%4];" \
                 : "=r"(r0), "=r"(r1), "=r"(r2), "=r"(r3) : "r"(addr))
__device__ __forceinline__ uint32_t h2pack(float a, float b) {
    __half2 t = __floats2half2_rn(a, b);
    return *reinterpret_cast<uint32_t*>(&t);
}

// ---------------- weight prep ----------------
__global__ void pack_wqkvT_h(const float* __restrict__ wq, const float* __restrict__ wk,
                             const float* __restrict__ wv, const float* __restrict__ bq,
                             const float* __restrict__ bk, const float* __restrict__ bv)
{
    int idx = blockIdx.x * blockDim.x + threadIdx.x;   // over H*D*DH = 1,048,576
    if (idx < NHEAD * DMODEL * DHEAD) {
        int e = idx & 63;
        int d = (idx >> 6) & 1023;
        int h = idx >> 16;
        int row = h * DHEAD + e;
        g_wqkvT[(size_t)row * DMODEL + d]          = __float2half(wq[idx] * QSCALE);
        g_wqkvT[(size_t)(1024 + row) * DMODEL + d] = __float2half(wk[idx]);
        g_wqkvT[(size_t)(2048 + row) * DMODEL + d] = __float2half(wv[idx]);
    }
    if (idx < NHEAD * DHEAD) {
        g_bqkv[idx]        = bq[idx] * QSCALE;
        g_bqkv[1024 + idx] = bk[idx];
        g_bqkv[2048 + idx] = bv[idx];
    }
}

// transpose fp32 [R][C] -> half [C][R]
__global__ void transpose_h(const float* __restrict__ in, __half* __restrict__ out,
                            int R, int C)
{
    __shared__ float t[32][33];
    int c0 = blockIdx.x * 32, r0 = blockIdx.y * 32;
    int x = threadIdx.x, y = threadIdx.y;   // 32 x 8
#pragma unroll
    for (int i = 0; i < 32; i += 8)
        t[y + i][x] = in[(size_t)(r0 + y + i) * C + c0 + x];
    __syncthreads();
#pragma unroll
    for (int i = 0; i < 32; i += 8)
        out[(size_t)(c0 + y + i) * R + r0 + x] = __float2half(t[x][y + i]);
}

__global__ void f2h_copy(const float* __restrict__ in, __half* __restrict__ out, int n4)
{
    int i = blockIdx.x * blockDim.x + threadIdx.x;
    if (i < n4) {
        float4 v = ((const float4*)in)[i];
        __half2 a = __floats2half2_rn(v.x, v.y);
        __half2 b = __floats2half2_rn(v.z, v.w);
        *(uint2*)(out + (size_t)i * 4) =
            make_uint2(*(uint32_t*)&a, *(uint32_t*)&b);
    }
}

// ---------------- fp16 mma GEMM: C[M,N] = A[M,K] * Bt[N,K]^T + bias ----------------
// BM=128, BN=128, BK=32 halves. 256 threads = 8 warps (2m x 4n), warp 64x32.
// pitch 40 halves (80B = 5*16B, coprime 8 -> ldmatrix conflict-free).
#define AP 40
__device__ __forceinline__ void ldt_h(const __half* g, int ldK, uint32_t sdst, int tid)
{
#pragma unroll
    for (int it = 0; it < 2; it++) {
        int c = tid + it * 256;
        int r = c >> 2, u = c & 3;
        cp16(sdst + (uint32_t)(r * (AP * 2) + u * 16), g + (size_t)r * ldK + u * 8);
    }
}

__global__ __launch_bounds__(256)
void gemm_h(const __half* __restrict__ A, const __half* __restrict__ B,
            const float* __restrict__ bias, float* __restrict__ C32,
            __half* __restrict__ C16, int M, int N, int K, int relu)
{
    __shared__ __half As[2][128 * AP];
    __shared__ __half Bs[2][128 * AP];
    const int tid = threadIdx.x, lane = tid & 31, wid = tid >> 5;
    const int grp = lane >> 2, tg = lane & 3;
    const int wm = wid & 1, wn = wid >> 1;
    const int m0 = blockIdx.y * 128, n0 = blockIdx.x * 128;
    const __half* Ab = A + (size_t)m0 * K;
    const __half* Bb = B + (size_t)n0 * K;
    const uint32_t sA = smem_u32(As), sB = smem_u32(Bs);
    const uint32_t BUFB = 128 * AP * 2;   // bytes per buffer

    float acc[4][4][4];
#pragma unroll
    for (int i = 0; i < 4; i++)
#pragma unroll
        for (int j = 0; j < 4; j++)
#pragma unroll
            for (int r = 0; r < 4; r++) acc[i][j][r] = 0.f;

    const int nk = K >> 5;
    ldt_h(Ab, K, sA, tid);
    ldt_h(Bb, K, sB, tid);
    asm volatile("cp.async.commit_group;" ::: "memory");

    for (int kk = 0; kk < nk; kk++) {
        const int buf = kk & 1;
        if (kk + 1 < nk) {
            ldt_h(Ab + (kk + 1) * 32, K, sA + (1 - buf) * BUFB, tid);
            ldt_h(Bb + (kk + 1) * 32, K, sB + (1 - buf) * BUFB, tid);
            asm volatile("cp.async.commit_group;" ::: "memory");
            asm volatile("cp.async.wait_group 1;" ::: "memory");
        } else {
            asm volatile("cp.async.wait_group 0;" ::: "memory");
        }
        __syncthreads();

        const uint32_t a_s = sA + buf * BUFB, b_s = sB + buf * BUFB;
#pragma unroll
        for (int ks = 0; ks < 2; ks++) {
            uint32_t ra[4][4], rb[4][2];
#pragma unroll
            for (int mt = 0; mt < 4; mt++) {
                uint32_t ad = a_s + (uint32_t)((wm * 64 + mt * 16 + (lane & 15)) * (AP * 2)
                                               + (ks * 2 + (lane >> 4)) * 16);
                LDSM4(ra[mt][0], ra[mt][1], ra[mt][2], ra[mt][3], ad);
            }
#pragma unroll
            for (int ntp = 0; ntp < 2; ntp++) {
                uint32_t r0, r1, r2, r3;
                uint32_t ad = b_s + (uint32_t)((wn * 32 + ntp * 16 + (lane & 15)) * (AP * 2)
                                               + (ks * 2 + (lane >> 4)) * 16);
                LDSM4(r0, r1, r2, r3, ad);
                rb[2 * ntp][0] = r0;     rb[2 * ntp][1] = r2;
                rb[2 * ntp + 1][0] = r1; rb[2 * ntp + 1][1] = r3;
            }
#pragma unroll
            for (int mt = 0; mt < 4; mt++)
#pragma unroll
                for (int nt = 0; nt < 4; nt++)
                    mma_f16(acc[mt][nt], ra[mt], rb[nt]);
        }
        __syncthreads();
    }

    // epilogue
#pragma unroll
    for (int mt = 0; mt < 4; mt++) {
#pragma unroll
        for (int nt = 0; nt < 4; nt++) {
            int row = m0 + wm * 64 + mt * 16 + grp;
            int col = n0 + wn * 32 + nt * 8 + tg * 2;
            float b0 = bias[col], b1 = bias[col + 1];
            float v00 = acc[mt][nt][0] + b0, v01 = acc[mt][nt][1] + b1;
            float v10 = acc[mt][nt][2] + b0, v11 = acc[mt][nt][3] + b1;
            if (relu) {
                v00 = fmaxf(v00, 0.f); v01 = fmaxf(v01, 0.f);
                v10 = fmaxf(v10, 0.f); v11 = fmaxf(v11, 0.f);
            }
            if (C16) {
                *(__half2*)(C16 + (size_t)row * N + col)       = __floats2half2_rn(v00, v01);
                *(__half2*)(C16 + (size_t)(row + 8) * N + col) = __floats2half2_rn(v10, v11);
            } else {
                *(float2*)(C32 + (size_t)row * N + col)       = make_float2(v00, v01);
                *(float2*)(C32 + (size_t)(row + 8) * N + col) = make_float2(v10, v11);
            }
        }
    }
}

// ---------------- fp16 mma flash attention ----------------
// CTA: 256 threads (8 warps), 128 q-rows, k-tiles of 64. DH=64.
// smem pitch 144B/row (9*16B, coprime 8). Q: 128*144, K/V double-buffered 64*144 each.
#define FQB 18432                      // Q bytes
#define FKV 9216                       // one K or V tile bytes
#define FLASH_SMEM (FQB + 2 * 2 * FKV) // 55296

__global__ __launch_bounds__(256) void flash_h(const __half* __restrict__ qkv,
                                               __half* __restrict__ attn)
{
    extern __shared__ __align__(16) char fsm[];
    const uint32_t sbase = smem_u32(fsm);
    const int tid = threadIdx.x, lane = tid & 31, wid = tid >> 5;
    const int grp = lane >> 2, tg = lane & 3;
    const int b = blockIdx.y >> 4, h = blockIdx.y & 15;
    const int q0 = blockIdx.x * 128;

    const __half* Qg = qkv + ((size_t)(b * SEQ + q0)) * QKVN + h * DHEAD;
    const __half* Kg = qkv + (size_t)b * SEQ * QKVN + 1024 + h * DHEAD;
    const __half* Vg = Kg + 1024;

    // Q loads
#pragma unroll
    for (int it = 0; it < 4; it++) {
        int c = tid + it * 256;
        int r = c >> 3, u = c & 7;
        cp16(sbase + (uint32_t)(r * 144 + u * 16), Qg + (size_t)r * QKVN + u * 8);
    }
    asm volatile("cp.async.commit_group;" ::: "memory");

    // KV tile 0
    {
#pragma unroll
        for (int it = 0; it < 4; it++) {
            int c = tid + it * 256;
            int mv = c >> 9, cc = c & 511;
            int r = cc >> 3, u = cc & 7;
            const __half* src = (mv ? Vg : Kg) + (size_t)r * QKVN + u * 8;
            cp16(sbase + FQB + (uint32_t)(mv * FKV + r * 144 + u * 16), src);
        }
        asm volatile("cp.async.commit_group;" ::: "memory");
    }

    uint32_t qf[4][4];
    float oacc[8][4];
    float m_run[2] = {-1e30f, -1e30f}, l_run[2] = {0.f, 0.f};
#pragma unroll
    for (int nt = 0; nt < 8; nt++)
#pragma unroll
        for (int j = 0; j < 4; j++) oacc[nt][j] = 0.f;

    const int NT = SEQ / 64;   // 32
    for (int kt = 0; kt < NT; kt++) {
        const int buf = kt & 1;
        if (kt + 1 < NT) {
#pragma unroll
            for (int it = 0; it < 4; it++) {
                int c = tid + it * 256;
                int mv = c >> 9, cc = c & 511;
                int r = cc >> 3, u = cc & 7;
                const __half* src = (mv ? Vg : Kg) + (size_t)((kt + 1) * 64 + r) * QKVN + u * 8;
                cp16(sbase + FQB + (uint32_t)((1 - buf) * 2 * FKV + mv * FKV + r * 144 + u * 16), src);
            }
            asm volatile("cp.async.commit_group;" ::: "memory");
            asm volatile("cp.async.wait_group 1;" ::: "memory");
        } else {
            asm volatile("cp.async.wait_group 0;" ::: "memory");
        }
        __syncthreads();

        if (kt == 0) {
#pragma unroll
            for (int ks = 0; ks < 4; ks++) {
                uint32_t ad = sbase + (uint32_t)((wid * 16 + (lane & 15)) * 144
                                                 + (ks * 2 + (lane >> 4)) * 16);
                LDSM4(qf[ks][0], qf[ks][1], qf[ks][2], qf[ks][3], ad);
            }
        }

        // S = Q * K^T
        float sacc[8][4];
#pragma unroll
        for (int nt = 0; nt < 8; nt++)
#pragma unroll
            for (int j = 0; j < 4; j++) sacc[nt][j] = 0.f;

        const uint32_t kbB = sbase + FQB + (uint32_t)(buf * 2 * FKV);
#pragma unroll
        for (int ks = 0; ks < 4; ks++) {
#pragma unroll
            for (int ntp = 0; ntp < 4; ntp++) {
                uint32_t r0, r1, r2, r3;
                uint32_t ad = kbB + (uint32_t)((ntp * 16 + (lane & 15)) * 144
                                               + (ks * 2 + (lane >> 4)) * 16);
                LDSM4(r0, r1, r2, r3, ad);
                uint32_t be[2] = {r0, r2}, bo[2] = {r1, r3};
                mma_f16(sacc[2 * ntp],     qf[ks], be);
                mma_f16(sacc[2 * ntp + 1], qf[ks], bo);
            }
        }

        // online softmax (scores already in log2 units via QSCALE)
#pragma unroll
        for (int r = 0; r < 2; r++) {
            const int j = r * 2;
            float mx = -1e30f;
#pragma unroll
            for (int nt = 0; nt < 8; nt++)
                mx = fmaxf(mx, fmaxf(sacc[nt][j], sacc[nt][j + 1]));
            mx = fmaxf(mx, __shfl_xor_sync(0xffffffffu, mx, 1));
            mx = fmaxf(mx, __shfl_xor_sync(0xffffffffu, mx, 2));
            float mnew = fmaxf(m_run[r], mx);
            float corr = exp2f(m_run[r] - mnew);
            float ls = 0.f;
#pragma unroll
            for (int nt = 0; nt < 8; nt++) {
                float p0 = exp2f(sacc[nt][j] - mnew);
                float p1 = exp2f(sacc[nt][j + 1] - mnew);
                sacc[nt][j] = p0; sacc[nt][j + 1] = p1;
                ls += p0 + p1;
            }
            ls += __shfl_xor_sync(0xffffffffu, ls, 1);
            ls += __shfl_xor_sync(0xffffffffu, ls, 2);
            m_run[r] = mnew;
            l_run[r] = l_run[r] * corr + ls;
#pragma unroll
            for (int nt = 0; nt < 8; nt++) {
                oacc[nt][j] *= corr; oacc[nt][j + 1] *= corr;
            }
        }

        // P -> fp16 A-fragments (S frag layout == A frag layout)
        uint32_t pa[4][4];
#pragma unroll
        for (int kp = 0; kp < 4; kp++) {
            pa[kp][0] = h2pack(sacc[2 * kp][0],     sacc[2 * kp][1]);
            pa[kp][1] = h2pack(sacc[2 * kp][2],     sacc[2 * kp][3]);
            pa[kp][2] = h2pack(sacc[2 * kp + 1][0], sacc[2 * kp + 1][1]);
            pa[kp][3] = h2pack(sacc[2 * kp + 1][2], sacc[2 * kp + 1][3]);
        }

        // O += P * V   (V via ldmatrix.trans)
        const uint32_t vbB = kbB + FKV;
#pragma unroll
        for (int kp = 0; kp < 4; kp++) {
#pragma unroll
            for (int ntp = 0; ntp < 4; ntp++) {
                uint32_t r0, r1, r2, r3;
                uint32_t ad = vbB + (uint32_t)((kp * 16 + (lane & 15)) * 144
                                               + (ntp * 2 + (lane >> 4)) * 16);
                LDSM4T(r0, r1, r2, r3, ad);
                uint32_t be[2] = {r0, r1}, bo[2] = {r2, r3};
                mma_f16(oacc[2 * ntp],     pa[kp], be);
                mma_f16(oacc[2 * ntp + 1], pa[kp], bo);
            }
        }
        __syncthreads();
    }

    // epilogue
    const float inv0 = 1.f / l_run[0], inv1 = 1.f / l_run[1];
    const size_t row0 = (size_t)(b * SEQ + q0 + wid * 16 + grp);
#pragma unroll
    for (int nt = 0; nt < 8; nt++) {
        int col = h * DHEAD + nt * 8 + tg * 2;
        *(__half2*)(attn + row0 * DMODEL + col) =
            __floats2half2_rn(oacc[nt][0] * inv0, oacc[nt][1] * inv0);
        *(__half2*)(attn + (row0 + 8) * DMODEL + col) =
            __floats2half2_rn(oacc[nt][2] * inv1, oacc[nt][3] * inv1);
    }
}

// ---------------- residual add + LayerNorm (+ optional half copy) ----------------
__global__ __launch_bounds__(256) void add_ln(const float* __restrict__ a,
                                              const float* __restrict__ resid,
                                              const float* __restrict__ g,
                                              const float* __restrict__ bb,
                                              float* __restrict__ out,
                                              __half* __restrict__ out_h)
{
    const int row = blockIdx.x;
    const int tid = threadIdx.x;
    const float* ar = a     + (size_t)row * DMODEL;
    const float* rr = resid + (size_t)row * DMODEL;

    float v[4], s = 0.f, sq = 0.f;
#pragma unroll
    for (int u = 0; u < 4; u++) {
        int c = u * 256 + tid;
        float t = ar[c] + rr[c];
        v[u] = t; s += t; sq += t * t;
    }
#pragma unroll
    for (int mm = 16; mm; mm >>= 1) {
        s  += __shfl_xor_sync(0xffffffffu, s, mm);
        sq += __shfl_xor_sync(0xffffffffu, sq, mm);
    }
    __shared__ float rs[8], rq[8];
    int w = tid >> 5, l = tid & 31;
    if (l == 0) { rs[w] = s; rq[w] = sq; }
    __syncthreads();
    s = 0.f; sq = 0.f;
#pragma unroll
    for (int i = 0; i < 8; i++) { s += rs[i]; sq += rq[i]; }

    float mean = s * (1.f / DMODEL);
    float var  = sq * (1.f / DMODEL) - mean * mean;
    float rstd = rsqrtf(var + 1e-5f);
    float* orow = out + (size_t)row * DMODEL;
#pragma unroll
    for (int u = 0; u < 4; u++) {
        int c = u * 256 + tid;
        float ov = (v[u] - mean) * rstd * g[c] + bb[c];
        orow[c] = ov;
        if (out_h) out_h[(size_t)row * DMODEL + c] = __float2half(ov);
    }
}

// ---------------- launch ----------------
extern "C" void kernel_launch(void* const* d_in, const int* in_sizes, int n_in,
                              void* d_out, int out_size)
{
    const float* x    = (const float*)d_in[0];
    const float* wq   = (const float*)d_in[1];
    const float* bq   = (const float*)d_in[2];
    const float* wk   = (const float*)d_in[3];
    const float* bk   = (const float*)d_in[4];
    const float* wv   = (const float*)d_in[5];
    const float* bv   = (const float*)d_in[6];
    const float* wo   = (const float*)d_in[7];
    const float* bo   = (const float*)d_in[8];
    const float* ln1g = (const float*)d_in[9];
    const float* ln1b = (const float*)d_in[10];
    const float* w1   = (const float*)d_in[11];
    const float* b1   = (const float*)d_in[12];
    const float* w2   = (const float*)d_in[13];
    const float* b2   = (const float*)d_in[14];
    const float* ln2g = (const float*)d_in[15];
    const float* ln2b = (const float*)d_in[16];
    float* out = (float*)d_out;

    __half *wqkvT, *woT, *w1T, *w2T, *xh, *qkvh, *attnh, *yh, *ff1h;
    float *bqkv, *t1, *y, *ff2;
    cudaGetSymbolAddress((void**)&wqkvT, g_wqkvT);
    cudaGetSymbolAddress((void**)&bqkv,  g_bqkv);
    cudaGetSymbolAddress((void**)&woT,   g_woT);
    cudaGetSymbolAddress((void**)&w1T,   g_w1T);
    cudaGetSymbolAddress((void**)&w2T,   g_w2T);
    cudaGetSymbolAddress((void**)&xh,    g_xh);
    cudaGetSymbolAddress((void**)&qkvh,  g_qkvh);
    cudaGetSymbolAddress((void**)&attnh, g_attnh);
    cudaGetSymbolAddress((void**)&t1,    g_t1);
    cudaGetSymbolAddress((void**)&y,     g_y);
    cudaGetSymbolAddress((void**)&yh,    g_yh);
    cudaGetSymbolAddress((void**)&ff1h,  g_ff1h);
    cudaGetSymbolAddress((void**)&ff2,   g_ff2);

    cudaFuncSetAttribute(flash_h, cudaFuncAttributeMaxDynamicSharedMemorySize, FLASH_SMEM);

    // prep
    pack_wqkvT_h<<<(NHEAD * DMODEL * DHEAD + 255) / 256, 256>>>(wq, wk, wv, bq, bk, bv);
    transpose_h<<<dim3(DMODEL / 32, DMODEL / 32), dim3(32, 8)>>>(wo, woT, DMODEL, DMODEL);
    transpose_h<<<dim3(FFDIM / 32, DMODEL / 32), dim3(32, 8)>>>(w1, w1T, DMODEL, FFDIM);
    transpose_h<<<dim3(DMODEL / 32, FFDIM / 32), dim3(32, 8)>>>(w2, w2T, FFDIM, DMODEL);
    f2h_copy<<<(BS * DMODEL / 4 + 255) / 256, 256>>>(x, xh, BS * DMODEL / 4);

    // 1) QKV projection -> half (Q pre-scaled by log2e/8 via weights)
    gemm_h<<<dim3(QKVN / 128, BS / 128), 256>>>(xh, wqkvT, bqkv, nullptr, qkvh,
                                                BS, QKVN, DMODEL, 0);
    // 2) flash attention -> half
    flash_h<<<dim3(SEQ / 128, BATCH * NHEAD), 256, FLASH_SMEM>>>(qkvh, attnh);
    // 3) output projection -> fp32
    gemm_h<<<dim3(DMODEL / 128, BS / 128), 256>>>(attnh, woT, bo, t1, nullptr,
                                                  BS, DMODEL, DMODEL, 0);
    // 4) residual + LN1 -> y (fp32) + yh (half)
    add_ln<<<BS, 256>>>(t1, x, ln1g, ln1b, y, yh);
    // 5) FFN up (relu) -> half
    gemm_h<<<dim3(FFDIM / 128, BS / 128), 256>>>(yh, w1T, b1, nullptr, ff1h,
                                                 BS, FFDIM, DMODEL, 1);
    // 6) FFN down -> fp32
    gemm_h<<<dim3(DMODEL / 128, BS / 128), 256>>>(ff1h, w2T, b2, ff2, nullptr,
                                                  BS, DMODEL, FFDIM, 0);
    // 7) residual + LN2 -> final output
    add_ln<<<BS, 256>>>(ff2, y, ln2g, ln2b, out, nullptr);
}